// round 12
// baseline (speedup 1.0000x reference)
#include <cuda_runtime.h>
#include <cstdint>

#define TT   2048
#define DD   512
#define BB   64
#define NCTA 128
#define NTHR 256

// ---- device-global scratch (allocation-free per harness rules) ----
__device__ float g_Xt[(size_t)TT * DD * BB];   // [t][d][b] transposed input (256 MB)
__device__ float g_hT[2][DD * BB];             // double-buffered hidden, [d][b]
__device__ unsigned g_count = 0;               // barrier arrivals (self-resetting)
__device__ volatile unsigned g_gen = 0;        // barrier generation (monotonic across replays)

// ---------------------------------------------------------------------------
// Phase 0: transpose X[b][t][d] -> Xt[t][d][b] (coalesced both sides via tile)
// ---------------------------------------------------------------------------
__global__ void __launch_bounds__(NTHR) transpose_kernel(const float* __restrict__ X) {
    __shared__ float tile[64][65];
    const int t  = blockIdx.y;
    const int d0 = blockIdx.x << 6;
    for (int i = threadIdx.x; i < 4096; i += NTHR) {
        const int b = i >> 6, dd = i & 63;                 // dd fastest -> coalesced read
        tile[dd][b] = X[((size_t)b * TT + t) * DD + d0 + dd];
    }
    __syncthreads();
    for (int i = threadIdx.x; i < 4096; i += NTHR) {
        const int dd = i >> 6, b = i & 63;                 // b fastest -> coalesced write
        g_Xt[((size_t)t * DD + d0 + dd) * BB + b] = tile[dd][b];
    }
}

// ---- packed f32x2 helpers (ptxas won't emit FFMA2 from C++) ----
__device__ __forceinline__ unsigned long long pack_dup(float x) {
    unsigned long long r;
    asm("mov.b64 %0, {%1, %1};" : "=l"(r) : "f"(x));
    return r;
}
__device__ __forceinline__ unsigned long long fadd2_(unsigned long long a, unsigned long long b) {
    unsigned long long r;
    asm("add.rn.f32x2 %0, %1, %2;" : "=l"(r) : "l"(a), "l"(b));
    return r;
}
#define FFMA2(d, a, b) asm("fma.rn.f32x2 %0, %1, %2, %0;" : "+l"(d) : "l"(a), "l"(b))

// ---------------------------------------------------------------------------
// Grid barrier: generation counter, safe across graph replays (count returns
// to 0 every barrier; gen is monotonic so stale values can never false-pass).
// ---------------------------------------------------------------------------
__device__ __forceinline__ void grid_sync() {
    __syncthreads();
    if (threadIdx.x == 0) {
        __threadfence();                       // publish this CTA's hT stores
        const unsigned gen = g_gen;            // read BEFORE arriving
        if (atomicAdd(&g_count, 1u) == NCTA - 1u) {
            g_count = 0u;
            __threadfence();                   // reset visible before release
            g_gen = gen + 1u;
        } else {
            while (g_gen == gen) __nanosleep(32);
        }
        __threadfence();
    }
    __syncthreads();
}

// ---------------------------------------------------------------------------
// Persistent recurrence kernel. CTA r owns output columns c0=4r..4r+3.
// 8 warps: warps 0-3 consume the h-half of `joined`, warps 4-7 the x-half.
// Lane (bg = lane&15, kh = lane>>4): 4 batch rows (b0=4*bg), 64 k's per kh.
// Accumulators: per bsub, two f32x2 pairs = (c0,c1),(c2,c3) for each matrix.
// ---------------------------------------------------------------------------
__global__ void __launch_bounds__(NTHR, 1) recur_kernel(
    const float* __restrict__ Wg, const float* __restrict__ bgv,
    const float* __restrict__ Wc, const float* __restrict__ bcv,
    float* __restrict__ out)
{
    __shared__ float4 sWg4[1024];          // 16 KB  W_gate[k][c0..c0+3]
    __shared__ float4 sWc4[1024];          // 16 KB
    __shared__ ulonglong2 red[512];        //  8 KB  cross-warp partial sums

    const int tid  = threadIdx.x;
    const int wid  = tid >> 5, lane = tid & 31;
    const int bgl  = lane & 15, kh = lane >> 4;
    const int c0   = blockIdx.x << 2;
    const bool isH = wid < 4;
    const int part = (wid & 3) * 128 + kh * 64;        // k offset within 512-half
    const int woff = part + (isH ? 0 : 512);           // row in joined-k space
    const int f4b  = part * 16 + bgl;                  // float4 index of (k=part, b0)

    // Load this CTA's weight columns (once)
    for (int k = tid; k < 1024; k += NTHR) {
        sWg4[k] = __ldg((const float4*)(Wg + (size_t)k * DD + c0));
        sWc4[k] = __ldg((const float4*)(Wc + (size_t)k * DD + c0));
    }
    // Zero this CTA's slice of h buffer 0
    g_hT[0][(blockIdx.x << 8) + tid] = 0.0f;

    const int cb = tid >> 6, bb = tid & 63;            // combine-phase (c, b)
    const float biasg = bgv[c0 + cb];
    const float biasc = bcv[c0 + cb];
    float h_reg = 0.0f;                                // this thread's own h[b][c]

    const ulonglong2* wgp = (const ulonglong2*)(sWg4 + woff);
    const ulonglong2* wcp = (const ulonglong2*)(sWc4 + woff);

    grid_sync();   // weights + zeroed h visible everywhere

    for (int t = 0; t < TT; t++) {
        const int cur = t & 1;
        const float4* src = isH
            ? ((const float4*)g_hT[cur] + f4b)
            : ((const float4*)g_Xt + (size_t)t * (DD * BB / 4) + f4b);

        unsigned long long ag00=0, ag01=0, ag10=0, ag11=0,
                           ag20=0, ag21=0, ag30=0, ag31=0;
        unsigned long long ac00=0, ac01=0, ac10=0, ac11=0,
                           ac20=0, ac21=0, ac30=0, ac31=0;

        #pragma unroll 8
        for (int kk = 0; kk < 64; kk++) {
            const float4 s      = __ldcg(src + kk * 16);   // L2-coherent broadcast read
            const ulonglong2 g2 = wgp[kk];                 // (w_c0,w_c1),(w_c2,w_c3)
            const ulonglong2 c2 = wcp[kk];
            const unsigned long long s0 = pack_dup(s.x), s1 = pack_dup(s.y),
                                     s2 = pack_dup(s.z), s3 = pack_dup(s.w);
            FFMA2(ag00, s0, g2.x); FFMA2(ag01, s0, g2.y);
            FFMA2(ag10, s1, g2.x); FFMA2(ag11, s1, g2.y);
            FFMA2(ag20, s2, g2.x); FFMA2(ag21, s2, g2.y);
            FFMA2(ag30, s3, g2.x); FFMA2(ag31, s3, g2.y);
            FFMA2(ac00, s0, c2.x); FFMA2(ac01, s0, c2.y);
            FFMA2(ac10, s1, c2.x); FFMA2(ac11, s1, c2.y);
            FFMA2(ac20, s2, c2.x); FFMA2(ac21, s2, c2.y);
            FFMA2(ac30, s3, c2.x); FFMA2(ac31, s3, c2.y);
        }

        // Reduce the two k-halves (kh) within each warp
        ag00 = fadd2_(ag00, __shfl_xor_sync(0xffffffffu, ag00, 16));
        ag01 = fadd2_(ag01, __shfl_xor_sync(0xffffffffu, ag01, 16));
        ag10 = fadd2_(ag10, __shfl_xor_sync(0xffffffffu, ag10, 16));
        ag11 = fadd2_(ag11, __shfl_xor_sync(0xffffffffu, ag11, 16));
        ag20 = fadd2_(ag20, __shfl_xor_sync(0xffffffffu, ag20, 16));
        ag21 = fadd2_(ag21, __shfl_xor_sync(0xffffffffu, ag21, 16));
        ag30 = fadd2_(ag30, __shfl_xor_sync(0xffffffffu, ag30, 16));
        ag31 = fadd2_(ag31, __shfl_xor_sync(0xffffffffu, ag31, 16));
        ac00 = fadd2_(ac00, __shfl_xor_sync(0xffffffffu, ac00, 16));
        ac01 = fadd2_(ac01, __shfl_xor_sync(0xffffffffu, ac01, 16));
        ac10 = fadd2_(ac10, __shfl_xor_sync(0xffffffffu, ac10, 16));
        ac11 = fadd2_(ac11, __shfl_xor_sync(0xffffffffu, ac11, 16));
        ac20 = fadd2_(ac20, __shfl_xor_sync(0xffffffffu, ac20, 16));
        ac21 = fadd2_(ac21, __shfl_xor_sync(0xffffffffu, ac21, 16));
        ac30 = fadd2_(ac30, __shfl_xor_sync(0xffffffffu, ac30, 16));
        ac31 = fadd2_(ac31, __shfl_xor_sync(0xffffffffu, ac31, 16));

        // ---- phase A: gate partials -> smem -> per-(b,c) combine ----
        if (lane < 16) {
            ulonglong2* dst = red + (((wid << 4) + lane) << 2);
            dst[0] = make_ulonglong2(ag00, ag01);
            dst[1] = make_ulonglong2(ag10, ag11);
            dst[2] = make_ulonglong2(ag20, ag21);
            dst[3] = make_ulonglong2(ag30, ag31);
        }
        __syncthreads();
        const float* redF = (const float*)red;
        float sg = biasg;
        #pragma unroll
        for (int w = 0; w < 8; w++)
            sg += redF[((((w << 4) + (bb >> 2)) << 2) + (bb & 3)) * 4 + cb];
        const float gate = 1.0f / (1.0f + __expf(-sg));
        __syncthreads();

        // ---- phase B: candidate partials ----
        if (lane < 16) {
            ulonglong2* dst = red + (((wid << 4) + lane) << 2);
            dst[0] = make_ulonglong2(ac00, ac01);
            dst[1] = make_ulonglong2(ac10, ac11);
            dst[2] = make_ulonglong2(ac20, ac21);
            dst[3] = make_ulonglong2(ac30, ac31);
        }
        __syncthreads();
        float sc = biasc;
        #pragma unroll
        for (int w = 0; w < 8; w++)
            sc += redF[((((w << 4) + (bb >> 2)) << 2) + (bb & 3)) * 4 + cb];
        const float cand = tanhf(sc);

        h_reg = gate * h_reg + (1.0f - gate) * cand;

        if (t == TT - 1) {
            out[(size_t)bb * DD + c0 + cb] = h_reg;    // final h [B, D]
        } else {
            g_hT[cur ^ 1][((c0 + cb) << 6) + bb] = h_reg;
            grid_sync();
        }
    }
}

extern "C" void kernel_launch(void* const* d_in, const int* in_sizes, int n_in,
                              void* d_out, int out_size) {
    (void)in_sizes; (void)n_in; (void)out_size;
    const float* X  = (const float*)d_in[0];
    const float* Wg = (const float*)d_in[1];
    const float* bg = (const float*)d_in[2];
    const float* Wc = (const float*)d_in[3];
    const float* bc = (const float*)d_in[4];
    float* out = (float*)d_out;

    transpose_kernel<<<dim3(DD / 64, TT), NTHR>>>(X);
    recur_kernel<<<NCTA, NTHR>>>(Wg, bg, Wc, bc, out);
}

// round 14
// speedup vs baseline: 1.1375x; 1.1375x over previous
#include <cuda_runtime.h>
#include <cstdint>

#define TT   2048
#define DD   512
#define BB   64
#define NCTA 128
#define NTHR 256

typedef unsigned long long ull;

// ---- device-global scratch (allocation-free per harness rules) ----
__device__ float g_Xt[(size_t)TT * DD * BB];          // [t][d][b] transposed input (256 MB)
__device__ float g_H[(size_t)(TT + 1) * DD * BB];     // [t][d][b] per-step hidden (268 MB)
__device__ int   g_flag[NCTA];                        // steps completed per CTA

// ---------------------------------------------------------------------------
// Reset: zero flags and h[0]. grid 128 x 256 = 32768 threads = DD*BB exactly.
// ---------------------------------------------------------------------------
__global__ void __launch_bounds__(NTHR) reset_kernel() {
    const int idx = blockIdx.x * NTHR + threadIdx.x;
    if (idx < NCTA) g_flag[idx] = 0;
    g_H[idx] = 0.0f;
}

// ---------------------------------------------------------------------------
// Transpose X[b][t][d] -> Xt[t][d][b] (coalesced both sides via smem tile)
// ---------------------------------------------------------------------------
__global__ void __launch_bounds__(NTHR) transpose_kernel(const float* __restrict__ X) {
    __shared__ float tile[64][65];
    const int t  = blockIdx.y;
    const int d0 = blockIdx.x << 6;
    for (int i = threadIdx.x; i < 4096; i += NTHR) {
        const int b = i >> 6, dd = i & 63;
        tile[dd][b] = X[((size_t)b * TT + t) * DD + d0 + dd];
    }
    __syncthreads();
    for (int i = threadIdx.x; i < 4096; i += NTHR) {
        const int dd = i >> 6, b = i & 63;
        g_Xt[((size_t)t * DD + d0 + dd) * BB + b] = tile[dd][b];
    }
}

// ---- packed f32x2 helpers (ptxas won't emit FFMA2/FADD2 from C++) ----
__device__ __forceinline__ ull pack_dup(float x) {
    ull r;
    asm("mov.b64 %0, {%1, %1};" : "=l"(r) : "f"(x));
    return r;
}
__device__ __forceinline__ ull fadd2_(ull a, ull b) {
    ull r;
    asm("add.rn.f32x2 %0, %1, %2;" : "=l"(r) : "l"(a), "l"(b));
    return r;
}
#define FFMA2(d, a, b) asm("fma.rn.f32x2 %0, %1, %2, %0;" : "+l"(d) : "l"(a), "l"(b))

// ---------------------------------------------------------------------------
// Persistent recurrence. 128 CTAs = 64 c-groups (8 cols) x 2 b-halves (32 b).
// Warps 0-3: h-half of joined (k 0..511), warps 4-7: x-half (k 512..1023).
// Lane: bgl = lane&15 -> b-pair (2 batch rows), kh = lane>>4 -> 64-k half.
// Accumulators: f32x2 over the b-pair, one per (mat, c) = 16 total.
// Dynamic smem: sWg dup 64KB | sWc dup 64KB | red 16KB  = 144KB.
// Sync: NO grid barrier. Producers flag their step; h-warps poll only their
// 16 producer CTAs. x-warps never wait (overlap h-poll + h-load latency).
// ---------------------------------------------------------------------------
extern __shared__ ull s_mem[];

__global__ void __launch_bounds__(NTHR, 1) recur_kernel(
    const float* __restrict__ Wg, const float* __restrict__ bgv,
    const float* __restrict__ Wc, const float* __restrict__ bcv,
    float* __restrict__ out)
{
    ull*   sWg = s_mem;                     // [1024 k][8 c] duplicated f32x2
    ull*   sWc = s_mem + 8192;
    float* red = (float*)(s_mem + 16384);   // [mat 2][warp 8][c 8][b 32]

    const int tid  = threadIdx.x;
    const int wid  = tid >> 5, lane = tid & 31;
    const int bgl  = lane & 15;             // b-pair group
    const int cg   = blockIdx.x >> 1;       // c-group (0..63)
    const int bh   = blockIdx.x & 1;        // b-half
    const int c0   = cg << 3;               // 8 output columns
    const int bbase = bh << 5;              // 32 batch rows
    const bool isH = wid < 4;
    const int kpart = (wid & 3) * 128 + (lane >> 4) * 64;  // k-offset within 512-half
    const int krow  = kpart + (isH ? 0 : 512);             // row in joined-k space

    // Load this CTA's weight columns, duplicated for f32x2 (once)
    for (int i = tid; i < 1024 * 8; i += NTHR) {
        const int k = i >> 3, c = i & 7;
        sWg[i] = pack_dup(__ldg(Wg + (size_t)k * DD + c0 + c));
        sWc[i] = pack_dup(__ldg(Wc + (size_t)k * DD + c0 + c));
    }

    const int cc = tid >> 5, bb = tid & 31;   // combine-phase (c, b)
    const float biasg = bgv[c0 + cc];
    const float biasc = bcv[c0 + cc];
    float h_reg = 0.0f;                       // this thread's own h[b][c]

    const ull* wgp = sWg + (size_t)krow * 8;  // weights for this warp's k-range
    const ull* wcp = sWc + (size_t)krow * 8;
    const int  bo  = (bbase >> 1) + bgl;      // ull offset of lane's b-pair in a d-row
    // producer CTA flag index for lanes 0..15 (h-warps): cg' = wid*16+lane, same bh
    const int  pidx = ((((wid & 3) << 4) | (lane & 15)) << 1) | bh;

    __syncthreads();   // weights visible

    for (int t = 0; t < TT; t++) {
        ull acc[2][8];
        #pragma unroll
        for (int m = 0; m < 2; m++)
            #pragma unroll
            for (int c = 0; c < 8; c++) acc[m][c] = 0ull;

        const ull* src;
        if (isH) {
            // wait for the 16 producer CTAs of this warp's k-range (this b-half)
            bool ready;
            do {
                const int f = (lane < 16) ? __ldcg(&g_flag[pidx]) : 0x7fffffff;
                ready = (f >= t);
            } while (!__all_sync(0xffffffffu, ready));
            src = (const ull*)(g_H + (size_t)t * (DD * BB)) + (size_t)kpart * (BB / 2) + bo;
        } else {
            src = (const ull*)(g_Xt + (size_t)t * (DD * BB)) + (size_t)kpart * (BB / 2) + bo;
        }

        #pragma unroll 8
        for (int kk = 0; kk < 64; kk++) {
            const ull s = __ldcg(src); src += BB / 2;      // b-pair, already packed
            const ulonglong2* wg2 = (const ulonglong2*)(wgp + (size_t)kk * 8);
            const ulonglong2* wc2 = (const ulonglong2*)(wcp + (size_t)kk * 8);
            #pragma unroll
            for (int j = 0; j < 4; j++) {
                const ulonglong2 g2 = wg2[j];
                FFMA2(acc[0][2*j],   s, g2.x);
                FFMA2(acc[0][2*j+1], s, g2.y);
                const ulonglong2 c2 = wc2[j];
                FFMA2(acc[1][2*j],   s, c2.x);
                FFMA2(acc[1][2*j+1], s, c2.y);
            }
        }

        // reduce the two 64-k halves (kh = lane>>4)
        #pragma unroll
        for (int m = 0; m < 2; m++)
            #pragma unroll
            for (int c = 0; c < 8; c++)
                acc[m][c] = fadd2_(acc[m][c], __shfl_xor_sync(0xffffffffu, acc[m][c], 16));

        // lanes 0..15 publish partials (conflict-free: 16 lanes x 8B contiguous)
        if (lane < 16) {
            #pragma unroll
            for (int m = 0; m < 2; m++)
                #pragma unroll
                for (int c = 0; c < 8; c++)
                    *(ull*)&red[(((m << 3) | wid) * 8 + c) * 32 + (lane << 1)] = acc[m][c];
        }
        __syncthreads();

        // combine: one (c,b) per thread; reads conflict-free (b contiguous)
        float sg = biasg, sc = biasc;
        #pragma unroll
        for (int w = 0; w < 8; w++) {
            sg += red[(w * 8 + cc) * 32 + bb];
            sc += red[((8 + w) * 8 + cc) * 32 + bb];
        }
        const float gate = __fdividef(1.0f, 1.0f + __expf(-sg));
        const float av = fabsf(sc);
        const float e  = __expf(-2.0f * av);
        const float th = __fdividef(1.0f - e, 1.0f + e);
        const float cand = (sc >= 0.0f) ? th : -th;
        h_reg = gate * h_reg + (1.0f - gate) * cand;

        if (t == TT - 1) {
            out[(size_t)(bbase + bb) * DD + c0 + cc] = h_reg;   // final h [B, D]
        } else {
            g_H[(size_t)(t + 1) * (DD * BB) + (size_t)(c0 + cc) * BB + bbase + bb] = h_reg;
            __threadfence();
            __syncthreads();   // also guards red WAR for next iteration
            if (tid == 0) *(volatile int*)&g_flag[blockIdx.x] = t + 1;
        }
    }
}

extern "C" void kernel_launch(void* const* d_in, const int* in_sizes, int n_in,
                              void* d_out, int out_size) {
    (void)in_sizes; (void)n_in; (void)out_size;
    const float* X  = (const float*)d_in[0];
    const float* Wg = (const float*)d_in[1];
    const float* bg = (const float*)d_in[2];
    const float* Wc = (const float*)d_in[3];
    const float* bc = (const float*)d_in[4];
    float* out = (float*)d_out;

    static bool attr_set = false;
    if (!attr_set) {
        cudaFuncSetAttribute(recur_kernel,
                             cudaFuncAttributeMaxDynamicSharedMemorySize, 148480);
        attr_set = true;
    }

    reset_kernel<<<NCTA, NTHR>>>();
    transpose_kernel<<<dim3(DD / 64, TT), NTHR>>>(X);
    recur_kernel<<<NCTA, NTHR, 147456>>>(Wg, bg, Wc, bc, out);
}

// round 15
// speedup vs baseline: 1.1926x; 1.0485x over previous
#include <cuda_runtime.h>
#include <cstdint>

#define TT   2048
#define DD   512
#define BB   64
#define NCTA 128
#define NTHR 512

typedef unsigned long long ull;

// ---- device-global scratch (allocation-free per harness rules) ----
__device__ float g_Xt[(size_t)TT * DD * BB];          // [t][d][b] transposed input
__device__ float g_H[(size_t)(TT + 1) * DD * BB];     // [t][d][b] per-step hidden
__device__ int   g_flag[NCTA];                        // steps completed per CTA

// ---------------------------------------------------------------------------
// Reset: zero flags and h[0]. 128 x 256 = 32768 threads = DD*BB exactly.
// ---------------------------------------------------------------------------
__global__ void __launch_bounds__(256) reset_kernel() {
    const int idx = blockIdx.x * 256 + threadIdx.x;
    if (idx < NCTA) g_flag[idx] = 0;
    g_H[idx] = 0.0f;
}

// ---------------------------------------------------------------------------
// Transpose X[b][t][d] -> Xt[t][d][b] (coalesced both sides via smem tile)
// ---------------------------------------------------------------------------
__global__ void __launch_bounds__(256) transpose_kernel(const float* __restrict__ X) {
    __shared__ float tile[64][65];
    const int t  = blockIdx.y;
    const int d0 = blockIdx.x << 6;
    for (int i = threadIdx.x; i < 4096; i += 256) {
        const int b = i >> 6, dd = i & 63;
        tile[dd][b] = X[((size_t)b * TT + t) * DD + d0 + dd];
    }
    __syncthreads();
    for (int i = threadIdx.x; i < 4096; i += 256) {
        const int dd = i >> 6, b = i & 63;
        g_Xt[((size_t)t * DD + d0 + dd) * BB + b] = tile[dd][b];
    }
}

// ---- packed f32x2 helpers (ptxas won't emit FFMA2/FADD2 from C++) ----
__device__ __forceinline__ ull pack_dup(float x) {
    ull r;
    asm("mov.b64 %0, {%1, %1};" : "=l"(r) : "f"(x));
    return r;
}
__device__ __forceinline__ ull fadd2_(ull a, ull b) {
    ull r;
    asm("add.rn.f32x2 %0, %1, %2;" : "=l"(r) : "l"(a), "l"(b));
    return r;
}
#define FFMA2(d, a, b) asm("fma.rn.f32x2 %0, %1, %2, %0;" : "+l"(d) : "l"(a), "l"(b))

// ---------------------------------------------------------------------------
// Persistent recurrence. 128 CTAs = 64 c-groups (8 cols) x 2 b-halves (32 b).
// 512 threads = 16 warps; warp w owns joined-k range [64w, 64w+64).
// Warps 0-7: h-half (k 0..511), warps 8-15: x-half (k 512..1023).
// Lane: bp = lane&15 -> b-pair (2 batch rows), kh = lane>>4 -> 32-k half.
// Accumulators: f32x2 over the b-pair, one per (mat, c) = 16 total.
// Dynamic smem: sWg dup 64KB | sWc dup 64KB | red 32KB = 160KB (1 CTA/SM).
// Sync: per-CTA ready flags; each h-warp polls only its 8 producer CTAs.
// 4 warps/SMSP hide poll + L2 latency behind other warps' FMA issue.
// ---------------------------------------------------------------------------
extern __shared__ ull s_mem[];

__global__ void __launch_bounds__(NTHR, 1) recur_kernel(
    const float* __restrict__ Wg, const float* __restrict__ bgv,
    const float* __restrict__ Wc, const float* __restrict__ bcv,
    float* __restrict__ out)
{
    ull*   sWg = s_mem;                     // [1024 k][8 c] duplicated f32x2
    ull*   sWc = s_mem + 8192;
    float* red = (float*)(s_mem + 16384);   // [mat 2][warp 16][c 8][b 32]

    const int tid  = threadIdx.x;
    const int wid  = tid >> 5, lane = tid & 31;
    const int bp   = lane & 15;             // b-pair within CTA's 32-b half
    const int kh   = lane >> 4;             // 32-k half within warp's 64 k
    const int cg   = blockIdx.x >> 1;       // c-group (0..63)
    const int bh   = blockIdx.x & 1;        // b-half
    const int c0   = cg << 3;               // 8 output columns
    const int bbase = bh << 5;              // 32 batch rows
    const bool isH = wid < 8;
    const int kpart = (wid & 7) * 64 + kh * 32;   // d-offset within 512 source rows
    const int krow  = wid * 64 + kh * 32;         // row in joined-k weight space

    // Load this CTA's weight columns, duplicated for f32x2 (once)
    for (int i = tid; i < 1024 * 8; i += NTHR) {
        const int k = i >> 3, c = i & 7;
        sWg[i] = pack_dup(__ldg(Wg + (size_t)k * DD + c0 + c));
        sWc[i] = pack_dup(__ldg(Wc + (size_t)k * DD + c0 + c));
    }

    const int cc = tid >> 5, bb = tid & 31;       // combine-phase (c, b), tid<256
    const float biasg = (tid < 256) ? bgv[c0 + cc] : 0.0f;
    const float biasc = (tid < 256) ? bcv[c0 + cc] : 0.0f;
    float h_reg = 0.0f;                           // this thread's own h[b][c]

    const ull* wgp = sWg + (size_t)krow * 8;      // weights for this lane's k-range
    const ull* wcp = sWc + (size_t)krow * 8;
    const int  bo  = (bbase >> 1) + bp;           // ull offset of lane's b-pair
    // producer CTA flag index for h-warps (lanes 0..7): cg' = 8*wid + lane
    const int  pidx = (((wid << 3) | (lane & 7)) << 1) | bh;

    __syncthreads();   // weights visible

    for (int t = 0; t < TT; t++) {
        ull acc[2][8];
        #pragma unroll
        for (int m = 0; m < 2; m++)
            #pragma unroll
            for (int c = 0; c < 8; c++) acc[m][c] = 0ull;

        const ull* src;
        if (isH) {
            // wait for the 8 producer CTAs of this warp's k-range (this b-half)
            bool ready;
            do {
                const int f = (lane < 8) ? __ldcg(&g_flag[pidx]) : 0x7fffffff;
                ready = (f >= t);
            } while (!__all_sync(0xffffffffu, ready));
            src = (const ull*)(g_H + (size_t)t * (DD * BB)) + (size_t)kpart * (BB / 2) + bo;
        } else {
            src = (const ull*)(g_Xt + (size_t)t * (DD * BB)) + (size_t)kpart * (BB / 2) + bo;
        }

        #pragma unroll 8
        for (int kk = 0; kk < 32; kk++) {
            const ull s = __ldcg(src); src += BB / 2;      // b-pair, already packed
            const ulonglong2* wg2 = (const ulonglong2*)(wgp + (size_t)kk * 8);
            const ulonglong2* wc2 = (const ulonglong2*)(wcp + (size_t)kk * 8);
            #pragma unroll
            for (int j = 0; j < 4; j++) {
                const ulonglong2 g2 = wg2[j];
                FFMA2(acc[0][2*j],   s, g2.x);
                FFMA2(acc[0][2*j+1], s, g2.y);
                const ulonglong2 c2 = wc2[j];
                FFMA2(acc[1][2*j],   s, c2.x);
                FFMA2(acc[1][2*j+1], s, c2.y);
            }
        }

        // reduce the two 32-k halves (kh) within each warp
        #pragma unroll
        for (int m = 0; m < 2; m++)
            #pragma unroll
            for (int c = 0; c < 8; c++)
                acc[m][c] = fadd2_(acc[m][c], __shfl_xor_sync(0xffffffffu, acc[m][c], 16));

        // lanes 0..15 publish partials (16 lanes x 8B contiguous per instr)
        if (lane < 16) {
            #pragma unroll
            for (int m = 0; m < 2; m++)
                #pragma unroll
                for (int c = 0; c < 8; c++)
                    *(ull*)&red[(((m << 4) | wid) * 8 + c) * 32 + (lane << 1)] = acc[m][c];
        }
        __syncthreads();

        if (tid < 256) {
            // combine: one (c,b) per thread; reads conflict-free (b contiguous)
            float sg = biasg, sc = biasc;
            #pragma unroll
            for (int w = 0; w < 16; w++) {
                sg += red[(w * 8 + cc) * 32 + bb];
                sc += red[((16 + w) * 8 + cc) * 32 + bb];
            }
            const float gate = __fdividef(1.0f, 1.0f + __expf(-sg));
            const float av = fabsf(sc);
            const float e  = __expf(-2.0f * av);
            const float th = __fdividef(1.0f - e, 1.0f + e);
            const float cand = (sc >= 0.0f) ? th : -th;
            h_reg = gate * h_reg + (1.0f - gate) * cand;

            if (t == TT - 1) {
                out[(size_t)(bbase + bb) * DD + c0 + cc] = h_reg;   // final h [B, D]
            } else {
                g_H[(size_t)(t + 1) * (DD * BB) + (size_t)(c0 + cc) * BB + bbase + bb] = h_reg;
                __threadfence();
            }
        }
        if (t < TT - 1) {
            __syncthreads();   // h published + red WAR guard for next iteration
            if (tid == 0) *(volatile int*)&g_flag[blockIdx.x] = t + 1;
        }
    }
}

extern "C" void kernel_launch(void* const* d_in, const int* in_sizes, int n_in,
                              void* d_out, int out_size) {
    (void)in_sizes; (void)n_in; (void)out_size;
    const float* X  = (const float*)d_in[0];
    const float* Wg = (const float*)d_in[1];
    const float* bg = (const float*)d_in[2];
    const float* Wc = (const float*)d_in[3];
    const float* bc = (const float*)d_in[4];
    float* out = (float*)d_out;

    static bool attr_set = false;
    if (!attr_set) {
        cudaFuncSetAttribute(recur_kernel,
                             cudaFuncAttributeMaxDynamicSharedMemorySize, 163840);
        attr_set = true;
    }

    reset_kernel<<<NCTA, 256>>>();
    transpose_kernel<<<dim3(DD / 64, TT), 256>>>(X);
    recur_kernel<<<NCTA, NTHR, 163840>>>(Wg, bg, Wc, bc, out);
}

// round 16
// speedup vs baseline: 1.2197x; 1.0227x over previous
#include <cuda_runtime.h>
#include <cstdint>

#define TT   2048
#define DD   512
#define BB   64
#define NCTA 128
#define NTHR 512

typedef unsigned long long ull;

// ---- device-global scratch (allocation-free per harness rules) ----
__device__ float g_Xt[(size_t)TT * DD * BB];          // [t][d][b] transposed input
__device__ float g_H[(size_t)(TT + 1) * DD * BB];     // [t][d][b] per-step hidden
__device__ int   g_flag[NCTA];                        // steps completed per CTA

// ---------------------------------------------------------------------------
// Reset: zero flags and h[0]. 128 x 256 = 32768 threads = DD*BB exactly.
// ---------------------------------------------------------------------------
__global__ void __launch_bounds__(256) reset_kernel() {
    const int idx = blockIdx.x * 256 + threadIdx.x;
    if (idx < NCTA) g_flag[idx] = 0;
    g_H[idx] = 0.0f;
}

// ---------------------------------------------------------------------------
// Transpose X[b][t][d] -> Xt[t][d][b] (coalesced both sides via smem tile)
// ---------------------------------------------------------------------------
__global__ void __launch_bounds__(256) transpose_kernel(const float* __restrict__ X) {
    __shared__ float tile[64][65];
    const int t  = blockIdx.y;
    const int d0 = blockIdx.x << 6;
    for (int i = threadIdx.x; i < 4096; i += 256) {
        const int b = i >> 6, dd = i & 63;
        tile[dd][b] = X[((size_t)b * TT + t) * DD + d0 + dd];
    }
    __syncthreads();
    for (int i = threadIdx.x; i < 4096; i += 256) {
        const int dd = i >> 6, b = i & 63;
        g_Xt[((size_t)t * DD + d0 + dd) * BB + b] = tile[dd][b];
    }
}

// ---- packed f32x2 helpers (ptxas won't emit FFMA2/FADD2 from C++) ----
__device__ __forceinline__ ull pack2(float lo, float hi) {
    ull r;
    asm("mov.b64 %0, {%1, %2};" : "=l"(r) : "f"(lo), "f"(hi));
    return r;
}
__device__ __forceinline__ ull pack_dup(float x) {
    ull r;
    asm("mov.b64 %0, {%1, %1};" : "=l"(r) : "f"(x));
    return r;
}
__device__ __forceinline__ ull fadd2_(ull a, ull b) {
    ull r;
    asm("add.rn.f32x2 %0, %1, %2;" : "=l"(r) : "l"(a), "l"(b));
    return r;
}
#define FFMA2(d, a, b) asm("fma.rn.f32x2 %0, %1, %2, %0;" : "+l"(d) : "l"(a), "l"(b))
#define UNPACK2(lo, hi, v) asm("mov.b64 {%0, %1}, %2;" : "=f"(lo), "=f"(hi) : "l"(v))

// ---------------------------------------------------------------------------
// Persistent recurrence. 128 CTAs = 64 c-groups (8 cols) x 2 b-halves (32 b).
// 512 threads = 16 warps; warp w owns joined-k rows [64w, 64w+64).
// Warps 0-7: h-half (k 0..511), warps 8-15: x-half (k 512..1023).
// Lane = batch element (32 lanes = CTA's 32 b). Per kk the whole warp reads
// ONE weight row: 4 broadcast LDS.128 of {gate,cand}-interleaved f32x2 pairs
// (1 wavefront each, conflict-free) + one coalesced 128B LDG.32 of the source.
// Accumulators: acc[c] f32x2 = (gate partial, cand partial) for c = 0..7.
// Dynamic smem: sW 64KB | red 32KB = 96KB (1 CTA/SM).
// Sync: per-CTA flags with st.release.gpu / ld.acquire.gpu (CG grid-sync
// pattern); each h-warp polls only its 8 producer CTAs.
// ---------------------------------------------------------------------------
extern __shared__ ull s_mem[];

__global__ void __launch_bounds__(NTHR, 1) recur_kernel(
    const float* __restrict__ Wg, const float* __restrict__ bgv,
    const float* __restrict__ Wc, const float* __restrict__ bcv,
    float* __restrict__ out)
{
    ull* sW  = s_mem;            // [1024 k][8 c] packed {w_gate, w_cand}
    ull* red = s_mem + 8192;     // [warp 16][c 8][b 32] packed partials

    const int tid  = threadIdx.x;
    const int wid  = tid >> 5, lane = tid & 31;
    const int cg   = blockIdx.x >> 1;       // c-group (0..63)
    const int bh   = blockIdx.x & 1;        // b-half
    const int c0   = cg << 3;               // 8 output columns
    const int bbase = bh << 5;              // 32 batch rows
    const bool isH = wid < 8;
    const int krow  = wid << 6;             // joined-k base for this warp
    const int dbase = (wid & 7) << 6;       // source row base within its half

    // Load this CTA's weight columns, {gate,cand}-interleaved (once)
    for (int i = tid; i < 8192; i += NTHR) {
        const int k = i >> 3, c = i & 7;
        sW[i] = pack2(__ldg(Wg + (size_t)k * DD + c0 + c),
                      __ldg(Wc + (size_t)k * DD + c0 + c));
    }

    const int cc = tid >> 5, bb = tid & 31;       // combine-phase (c, b), tid<256
    const float biasg = (tid < 256) ? bgv[c0 + cc] : 0.0f;
    const float biasc = (tid < 256) ? bcv[c0 + cc] : 0.0f;
    float h_reg = 0.0f;                           // this thread's own h[b][c]

    // producer CTA flag index for h-warps (lanes 0..7): cg' = 8*wid + lane
    const int pidx = (((wid << 3) | (lane & 7)) << 1) | bh;

    __syncthreads();   // weights visible

    for (int t = 0; t < TT; t++) {
        const float* src = (isH ? g_H + (size_t)t * (DD * BB)
                                : g_Xt + (size_t)t * (DD * BB))
                           + (size_t)dbase * BB + bbase + lane;

        if (isH) {
            // wait for the 8 producer CTAs of this warp's d-range (this b-half)
            bool ready;
            do {
                int f = 0x7fffffff;
                if (lane < 8)
                    asm volatile("ld.acquire.gpu.global.b32 %0, [%1];"
                                 : "=r"(f) : "l"(g_flag + pidx) : "memory");
                ready = (f >= t);
            } while (!__all_sync(0xffffffffu, ready));
        }

        ull acc0 = 0, acc1 = 0, acc2 = 0, acc3 = 0,
            acc4 = 0, acc5 = 0, acc6 = 0, acc7 = 0;
        const ulonglong2* wp = (const ulonglong2*)(sW + ((size_t)krow << 3));

        #pragma unroll 8
        for (int kk = 0; kk < 64; kk++) {
            const float s = __ldcg(src); src += BB;        // coalesced 128B row
            const ull sd = pack_dup(s);
            const ulonglong2 w01 = wp[0], w23 = wp[1], w45 = wp[2], w67 = wp[3];
            wp += 4;                                        // broadcast LDS.128 x4
            FFMA2(acc0, sd, w01.x); FFMA2(acc1, sd, w01.y);
            FFMA2(acc2, sd, w23.x); FFMA2(acc3, sd, w23.y);
            FFMA2(acc4, sd, w45.x); FFMA2(acc5, sd, w45.y);
            FFMA2(acc6, sd, w67.x); FFMA2(acc7, sd, w67.y);
        }

        // publish 16 warp-partials per (c,b): 8 STS.64, 32 lanes contiguous
        {
            ull* dst = red + ((wid << 8) | lane);   // red[wid][c][lane]
            dst[0 * 32] = acc0; dst[1 * 32] = acc1;
            dst[2 * 32] = acc2; dst[3 * 32] = acc3;
            dst[4 * 32] = acc4; dst[5 * 32] = acc5;
            dst[6 * 32] = acc6; dst[7 * 32] = acc7;
        }
        __syncthreads();

        if (tid < 256) {
            // combine: one (c,b) per thread; reads contiguous over b
            const ull* rp = red + ((cc << 5) | bb);
            ull t0 = 0, t1 = 0;
            #pragma unroll
            for (int w = 0; w < 16; w += 2) {
                t0 = fadd2_(t0, rp[(w) << 8]);
                t1 = fadd2_(t1, rp[(w + 1) << 8]);
            }
            const ull tot = fadd2_(t0, t1);
            float sg, sc;
            UNPACK2(sg, sc, tot);
            sg += biasg; sc += biasc;
            const float gate = __fdividef(1.0f, 1.0f + __expf(-sg));
            const float av = fabsf(sc);
            const float e  = __expf(-2.0f * av);
            const float th = __fdividef(1.0f - e, 1.0f + e);
            const float cand = (sc >= 0.0f) ? th : -th;
            h_reg = gate * h_reg + (1.0f - gate) * cand;

            if (t == TT - 1) {
                out[(size_t)(bbase + bb) * DD + c0 + cc] = h_reg;   // final h [B, D]
            } else {
                g_H[(size_t)(t + 1) * (DD * BB) + (size_t)(c0 + cc) * BB + bbase + bb] = h_reg;
            }
        }
        if (t < TT - 1) {
            __syncthreads();   // h stores ordered-before release; red WAR guard
            if (tid == 0)
                asm volatile("st.release.gpu.global.b32 [%0], %1;"
                             :: "l"(g_flag + blockIdx.x), "r"(t + 1) : "memory");
        }
    }
}

extern "C" void kernel_launch(void* const* d_in, const int* in_sizes, int n_in,
                              void* d_out, int out_size) {
    (void)in_sizes; (void)n_in; (void)out_size;
    const float* X  = (const float*)d_in[0];
    const float* Wg = (const float*)d_in[1];
    const float* bg = (const float*)d_in[2];
    const float* Wc = (const float*)d_in[3];
    const float* bc = (const float*)d_in[4];
    float* out = (float*)d_out;

    static bool attr_set = false;
    if (!attr_set) {
        cudaFuncSetAttribute(recur_kernel,
                             cudaFuncAttributeMaxDynamicSharedMemorySize, 100352);
        attr_set = true;
    }

    reset_kernel<<<NCTA, 256>>>();
    transpose_kernel<<<dim3(DD / 64, TT), 256>>>(X);
    recur_kernel<<<NCTA, NTHR, 98304>>>(Wg, bg, Wc, bc, out);
}

// round 17
// speedup vs baseline: 1.4139x; 1.1592x over previous
#include <cuda_runtime.h>
#include <cstdint>

#define TT   2048
#define DD   512
#define BB   64
#define NCTA 128
#define NTHR 512

typedef unsigned long long ull;

// ---- device-global scratch (allocation-free per harness rules) ----
__device__ float g_Xt[(size_t)TT * DD * BB];          // [t][d][b] transposed input
__device__ float g_H[(size_t)(TT + 1) * DD * BB];     // [t][d][b] per-step hidden
__device__ int   g_flagT[2 * DD];                     // [bh][row] row-granular flags

__global__ void dummy_kernel() {}                     // profiler window alignment

// ---------------------------------------------------------------------------
// Reset: zero row-flags and h[0]. 128 x 256 = 32768 threads = DD*BB exactly.
// ---------------------------------------------------------------------------
__global__ void __launch_bounds__(256) reset_kernel() {
    const int idx = blockIdx.x * 256 + threadIdx.x;
    if (idx < 2 * DD) g_flagT[idx] = 0;
    g_H[idx] = 0.0f;
}

// ---------------------------------------------------------------------------
// Transpose X[b][t][d] -> Xt[t][d][b] (coalesced both sides via smem tile)
// ---------------------------------------------------------------------------
__global__ void __launch_bounds__(256) transpose_kernel(const float* __restrict__ X) {
    __shared__ float tile[64][65];
    const int t  = blockIdx.y;
    const int d0 = blockIdx.x << 6;
    for (int i = threadIdx.x; i < 4096; i += 256) {
        const int b = i >> 6, dd = i & 63;
        tile[dd][b] = X[((size_t)b * TT + t) * DD + d0 + dd];
    }
    __syncthreads();
    for (int i = threadIdx.x; i < 4096; i += 256) {
        const int dd = i >> 6, b = i & 63;
        g_Xt[((size_t)t * DD + d0 + dd) * BB + b] = tile[dd][b];
    }
}

// ---- packed f32x2 helpers (ptxas won't emit FFMA2/FADD2 from C++) ----
__device__ __forceinline__ ull pack2(float lo, float hi) {
    ull r;
    asm("mov.b64 %0, {%1, %2};" : "=l"(r) : "f"(lo), "f"(hi));
    return r;
}
__device__ __forceinline__ ull pack_dup(float x) {
    ull r;
    asm("mov.b64 %0, {%1, %1};" : "=l"(r) : "f"(x));
    return r;
}
__device__ __forceinline__ ull fadd2_(ull a, ull b) {
    ull r;
    asm("add.rn.f32x2 %0, %1, %2;" : "=l"(r) : "l"(a), "l"(b));
    return r;
}
#define FFMA2(d, a, b) asm("fma.rn.f32x2 %0, %1, %2, %0;" : "+l"(d) : "l"(a), "l"(b))
#define UNPACK2(lo, hi, v) asm("mov.b64 {%0, %1}, %2;" : "=f"(lo), "=f"(hi) : "l"(v))

// 32-row partial-GEMM: src = one float per lane per row (coalesced 128B),
// weights = broadcast LDS.128 of {gate,cand}-interleaved pairs. Result -> red.
__device__ __forceinline__ void partial32(const float* __restrict__ src,
                                          const ulonglong2* __restrict__ wp,
                                          ull* __restrict__ dst) {
    ull a0 = 0, a1 = 0, a2 = 0, a3 = 0, a4 = 0, a5 = 0, a6 = 0, a7 = 0;
    #pragma unroll 8
    for (int kk = 0; kk < 32; kk++) {
        const float s = __ldcg(src); src += BB;
        const ull sd = pack_dup(s);
        const ulonglong2 w01 = wp[0], w23 = wp[1], w45 = wp[2], w67 = wp[3];
        wp += 4;
        FFMA2(a0, sd, w01.x); FFMA2(a1, sd, w01.y);
        FFMA2(a2, sd, w23.x); FFMA2(a3, sd, w23.y);
        FFMA2(a4, sd, w45.x); FFMA2(a5, sd, w45.y);
        FFMA2(a6, sd, w67.x); FFMA2(a7, sd, w67.y);
    }
    dst[0 * 32] = a0; dst[1 * 32] = a1; dst[2 * 32] = a2; dst[3 * 32] = a3;
    dst[4 * 32] = a4; dst[5 * 32] = a5; dst[6 * 32] = a6; dst[7 * 32] = a7;
}

// ---------------------------------------------------------------------------
// Persistent recurrence. 128 CTAs = 64 c-groups (8 cols) x 2 b-halves (32 b).
// 16 warps; warp w owns h-rows [32w,32w+32) AND x-rows [512+32w, 512+32w+32).
// Per step: x-partials (no wait) -> coalesced 128B poll of 32 row-flags ->
// h-partials -> ONE __syncthreads -> warps 0-7 combine one c-row each, store
// one 128B h-line, __syncwarp, lane0 st.release.gpu its row flag (staggered
// fine-grained publish; release drains 1 line, not 32).
// red double-buffered -> no WAR barrier. Dynamic smem: sW 64K | red 128K.
// ---------------------------------------------------------------------------
extern __shared__ ull s_mem[];

__global__ void __launch_bounds__(NTHR, 1) recur_kernel(
    const float* __restrict__ Wg, const float* __restrict__ bgv,
    const float* __restrict__ Wc, const float* __restrict__ bcv,
    float* __restrict__ out)
{
    ull* sW  = s_mem;            // [1024 k][8 c] packed {w_gate, w_cand}
    ull* red = s_mem + 8192;     // [buf 2][slot 32][c 8][b 32]

    const int tid  = threadIdx.x;
    const int wid  = tid >> 5, lane = tid & 31;
    const int cg   = blockIdx.x >> 1;       // c-group (0..63)
    const int bh   = blockIdx.x & 1;        // b-half
    const int c0   = cg << 3;               // 8 output columns
    const int bbase = bh << 5;              // 32 batch rows
    const int hrow0 = wid << 5;             // this warp's h-row base (d-space)

    // Load this CTA's weight columns, {gate,cand}-interleaved (once)
    for (int i = tid; i < 8192; i += NTHR) {
        const int k = i >> 3, c = i & 7;
        sW[i] = pack2(__ldg(Wg + (size_t)k * DD + c0 + c),
                      __ldg(Wc + (size_t)k * DD + c0 + c));
    }

    const bool isComb = (wid < 8);          // combine warp w handles c-row w
    const float biasg = isComb ? bgv[c0 + wid] : 0.0f;
    const float biasc = isComb ? bcv[c0 + wid] : 0.0f;
    float h_reg = 0.0f;                     // combine threads' own h[b][c]

    const int* myflag = g_flagT + bh * DD + hrow0 + lane;   // 32 consecutive words

    __syncthreads();   // weights visible

    for (int t = 0; t < TT; t++) {
        const int bt = t & 1;
        ull* const redbuf = red + (bt << 13);   // 32*8*32 = 8192 ull per buffer

        // ---- x-phase (independent of h; runs during producers' publish) ----
        partial32(g_Xt + (size_t)t * (DD * BB) + (size_t)hrow0 * BB + bbase + lane,
                  (const ulonglong2*)(sW + ((512 + hrow0) << 3)),
                  redbuf + (wid << 8) + lane);

        // ---- poll the 32 row-flags this warp consumes (one 128B load) ----
        {
            bool ready;
            do {
                int f;
                asm volatile("ld.acquire.gpu.global.b32 %0, [%1];"
                             : "=r"(f) : "l"(myflag) : "memory");
                ready = (f >= t);
            } while (!__all_sync(0xffffffffu, ready));
        }

        // ---- h-phase ----
        partial32(g_H + (size_t)t * (DD * BB) + (size_t)hrow0 * BB + bbase + lane,
                  (const ulonglong2*)(sW + (hrow0 << 3)),
                  redbuf + ((16 + wid) << 8) + lane);

        __syncthreads();   // all 32 partial-sets visible (ONLY bar this step)

        if (isComb) {
            // combine c-row = wid, b = lane: sum 32 packed partials
            const ull* rp = redbuf + (wid << 5) + lane;     // stride per slot: 256
            ull t0 = 0, t1 = 0, t2 = 0, t3 = 0;
            #pragma unroll
            for (int s = 0; s < 32; s += 4) {
                t0 = fadd2_(t0, rp[(s + 0) << 8]);
                t1 = fadd2_(t1, rp[(s + 1) << 8]);
                t2 = fadd2_(t2, rp[(s + 2) << 8]);
                t3 = fadd2_(t3, rp[(s + 3) << 8]);
            }
            const ull tot = fadd2_(fadd2_(t0, t1), fadd2_(t2, t3));
            float sg, sc;
            UNPACK2(sg, sc, tot);
            sg += biasg; sc += biasc;
            const float gate = __fdividef(1.0f, 1.0f + __expf(-sg));
            const float av = fabsf(sc);
            const float e  = __expf(-2.0f * av);
            const float th = __fdividef(1.0f - e, 1.0f + e);
            const float cand = (sc >= 0.0f) ? th : -th;
            h_reg = gate * h_reg + (1.0f - gate) * cand;

            if (t == TT - 1) {
                out[(size_t)(bbase + lane) * DD + c0 + wid] = h_reg;  // final [B,D]
            } else {
                // one 128B line per warp, then fine-grained release of its flag
                g_H[(size_t)(t + 1) * (DD * BB) + (size_t)(c0 + wid) * BB + bbase + lane] = h_reg;
                __syncwarp();
                if (lane == 0)
                    asm volatile("st.release.gpu.global.b32 [%0], %1;"
                                 :: "l"(g_flagT + bh * DD + c0 + wid), "r"(t + 1)
                                 : "memory");
            }
        }
        // no second barrier: next step's writes go to the other red buffer,
        // and step t+2 (same buffer) is fenced by the next step's syncthreads.
    }
}

extern "C" void kernel_launch(void* const* d_in, const int* in_sizes, int n_in,
                              void* d_out, int out_size) {
    (void)in_sizes; (void)n_in; (void)out_size;
    const float* X  = (const float*)d_in[0];
    const float* Wg = (const float*)d_in[1];
    const float* bg = (const float*)d_in[2];
    const float* Wc = (const float*)d_in[3];
    const float* bc = (const float*)d_in[4];
    float* out = (float*)d_out;

    static bool attr_set = false;
    if (!attr_set) {
        cudaFuncSetAttribute(recur_kernel,
                             cudaFuncAttributeMaxDynamicSharedMemorySize, 196608);
        attr_set = true;
    }

    dummy_kernel<<<1, 32>>>();     // shifts ncu's -s5 window toward recur_kernel
    reset_kernel<<<NCTA, 256>>>();
    transpose_kernel<<<dim3(DD / 64, TT), 256>>>(X);
    recur_kernel<<<NCTA, NTHR, 196608>>>(Wg, bg, Wc, bc, out);
}